// round 7
// baseline (speedup 1.0000x reference)
#include <cuda_runtime.h>
#include <stdint.h>

// TorchNeighborList on GB300 — R6 (R5 resubmit after infra failure, +__ldg/unroll).
//   * distances computed once (P, not 2P); second-half rank = r1 + (P - Vh)
//   * writeBulk: EVERY block does zero-fill slice then idx slice (grid-stride,
//     single wave) -> perfect DRAM load balance
//   * writeValid is a separate later kernel (ordered after writeBulk)

#define NA    1024
#define PCI   523776            // NA*(NA-1)/2
#define MAXB  256
#define CUT   5.0f
#define OUTB  1664              // outside-region pass1 blocks (13*1024/8)
#define CTRB  64                // center-region pass1 blocks
#define NB    1184              // writeBulk grid (148 SMs * 8 blocks)

__device__ unsigned d_mask[442368];     // P/32 = 442,352 words used
__device__ int      d_wpre[442368];
__device__ int      d_bsums[512];
__device__ int      d_bpre[512];
__device__ int      d_atomCount[NA];
__device__ int      d_atomBase[NA];
__device__ unsigned d_bucket[NA * MAXB];
__device__ int      d_Vh;               // valid count in first half
__device__ int      d_V;                // total valid = 2*Vh

__device__ __forceinline__ int rowstartC(int i) {
    return i * 1023 - (i * (i - 1)) / 2;
}

__device__ __forceinline__ void decodeCenter(int t2, int& i0, int& j0) {
    float q = (float)t2;
    float disc = __fsub_rn(1047552.25f, __fadd_rn(q, q));
    int i = (int)(1023.5f - __fsqrt_rn(disc));
    if (i < 0) i = 0;
    if (i > 1022) i = 1022;
    while (rowstartC(i + 1) <= t2) ++i;
    while (rowstartC(i) > t2) --i;
    i0 = i;
    j0 = t2 - rowstartC(i) + i + 1;
}

__global__ void initK() { d_atomCount[threadIdx.x] = 0; }

// ---- pass1: blocks [0,OUTB) outside rows, [OUTB,OUTB+CTRB) center pairs ----
__global__ void pass1(const float* __restrict__ pos, const float* __restrict__ box,
                      const int* __restrict__ shifts, long long P) {
    __shared__ float spx[NA], spy[NA], spz[NA];
    int tid = threadIdx.x;
    for (int k = tid; k < NA; k += 256) {
        spx[k] = pos[3 * k + 0];
        spy[k] = pos[3 * k + 1];
        spz[k] = pos[3 * k + 2];
    }
    __syncthreads();
    if (blockIdx.x < OUTB) {
        int rowBase = blockIdx.x * 8;
        #pragma unroll 1
        for (int rr = 0; rr < 8; rr++) {
            int row = rowBase + rr;
            int s = row >> 10, i = row & 1023;
            float s0 = (float)shifts[3 * s + 0];
            float s1 = (float)shifts[3 * s + 1];
            float s2 = (float)shifts[3 * s + 2];
            float svx = s0 * box[0] + s1 * box[3] + s2 * box[6];
            float svy = s0 * box[1] + s1 * box[4] + s2 * box[7];
            float svz = s0 * box[2] + s1 * box[5] + s2 * box[8];
            float pix = spx[i], piy = spy[i], piz = spz[i];
            int t2base = PCI + (row << 10);
            #pragma unroll
            for (int c = 0; c < 4; c++) {
                int j = c * 256 + tid;
                float dx = __fadd_rn(__fsub_rn(pix, spx[j]), svx);
                float dy = __fadd_rn(__fsub_rn(piy, spy[j]), svy);
                float dz = __fadd_rn(__fsub_rn(piz, spz[j]), svz);
                float r2 = __fadd_rn(__fadd_rn(__fmul_rn(dx, dx), __fmul_rn(dy, dy)),
                                     __fmul_rn(dz, dz));
                bool valid = __fsqrt_rn(r2) < CUT;
                unsigned b = __ballot_sync(0xFFFFFFFFu, valid);
                if ((tid & 31) == 0)
                    d_mask[(t2base >> 5) + c * 8 + (tid >> 5)] = b;
                if (valid) {
                    unsigned t2 = (unsigned)(t2base + j);
                    int sl = atomicAdd(&d_atomCount[i], 1);
                    if (sl < MAXB) d_bucket[i * MAXB + sl] = t2;
                    int s2a = atomicAdd(&d_atomCount[j], 1);
                    if (s2a < MAXB) d_bucket[j * MAXB + s2a] = t2 + (unsigned)P;
                }
            }
        }
    } else {
        int cb = blockIdx.x - OUTB;
        #pragma unroll 1
        for (int c = 0; c < 32; c++) {
            int t2 = cb * 8192 + c * 256 + tid;
            bool valid = false;
            int i0 = 0, j0 = 0;
            if (t2 < PCI) {
                decodeCenter(t2, i0, j0);
                float dx = __fsub_rn(spx[i0], spx[j0]);
                float dy = __fsub_rn(spy[i0], spy[j0]);
                float dz = __fsub_rn(spz[i0], spz[j0]);
                float r2 = __fadd_rn(__fadd_rn(__fmul_rn(dx, dx), __fmul_rn(dy, dy)),
                                     __fmul_rn(dz, dz));
                valid = __fsqrt_rn(r2) < CUT;
            }
            unsigned b = __ballot_sync(0xFFFFFFFFu, valid);
            int wb = cb * 256 + c * 8 + (tid >> 5);
            if ((tid & 31) == 0 && wb < (PCI >> 5))
                d_mask[wb] = b;
            if (valid) {
                int sl = atomicAdd(&d_atomCount[i0], 1);
                if (sl < MAXB) d_bucket[i0 * MAXB + sl] = (unsigned)t2;
                int s2a = atomicAdd(&d_atomCount[j0], 1);
                if (s2a < MAXB) d_bucket[j0 * MAXB + s2a] = (unsigned)(t2 + P);
            }
        }
    }
}

// ---- shuffle-based scans ----
__global__ void scanA(int W) {
    __shared__ int wsum[32];
    int tid = threadIdx.x, lane = tid & 31, wid = tid >> 5;
    int w = blockIdx.x * 1024 + tid;
    int v = (w < W) ? __popc(d_mask[w]) : 0;
    int x = v;
    #pragma unroll
    for (int o = 1; o < 32; o <<= 1) {
        int y = __shfl_up_sync(0xFFFFFFFFu, x, o);
        if (lane >= o) x += y;
    }
    if (lane == 31) wsum[wid] = x;
    __syncthreads();
    if (wid == 0) {
        int y = wsum[lane];
        #pragma unroll
        for (int o = 1; o < 32; o <<= 1) {
            int z = __shfl_up_sync(0xFFFFFFFFu, y, o);
            if (lane >= o) y += z;
        }
        wsum[lane] = y;
    }
    __syncthreads();
    int base = wid ? wsum[wid - 1] : 0;
    if (w < W) d_wpre[w] = base + x - v;
    if (tid == 0) d_bsums[blockIdx.x] = wsum[31];
}

__global__ void scanB(int nb) {
    __shared__ int wsum[32];
    int tid = threadIdx.x, lane = tid & 31, wid = tid >> 5;
    int v = (tid < nb) ? d_bsums[tid] : 0;
    int x = v;
    #pragma unroll
    for (int o = 1; o < 32; o <<= 1) {
        int y = __shfl_up_sync(0xFFFFFFFFu, x, o);
        if (lane >= o) x += y;
    }
    if (lane == 31) wsum[wid] = x;
    __syncthreads();
    if (wid == 0) {
        int y = wsum[lane];
        #pragma unroll
        for (int o = 1; o < 32; o <<= 1) {
            int z = __shfl_up_sync(0xFFFFFFFFu, y, o);
            if (lane >= o) y += z;
        }
        wsum[lane] = y;
    }
    __syncthreads();
    int base = wid ? wsum[wid - 1] : 0;
    if (tid < nb) d_bpre[tid] = base + x - v;
    if (tid == 0) { d_Vh = wsum[31]; d_V = 2 * wsum[31]; }
    __syncthreads();
    // atom exclusive scan
    int a = d_atomCount[tid];
    int xa = a;
    #pragma unroll
    for (int o = 1; o < 32; o <<= 1) {
        int y = __shfl_up_sync(0xFFFFFFFFu, xa, o);
        if (lane >= o) xa += y;
    }
    __syncthreads();
    if (lane == 31) wsum[wid] = xa;
    __syncthreads();
    if (wid == 0) {
        int y = wsum[lane];
        #pragma unroll
        for (int o = 1; o < 32; o <<= 1) {
            int z = __shfl_up_sync(0xFFFFFFFFu, y, o);
            if (lane >= o) y += z;
        }
        wsum[lane] = y;
    }
    __syncthreads();
    int basea = wid ? wsum[wid - 1] : 0;
    d_atomBase[tid] = basea + xa - a;
}

// ---- bulk writer: every block zero-fills a slice, then writes an idx slice ----
__global__ void writeBulk(long long P, long long TWOP, float* __restrict__ out) {
    int tid = threadIdx.x;
    long long g = (long long)blockIdx.x * 256 + tid;
    long long stride = (long long)NB * 256;

    // phase 1: zero offsets [2T,5T) + valid [5T,6T): TWOP float4s
    float4* p = (float4*)(out + 2 * TWOP);
    float4 z = make_float4(0.f, 0.f, 0.f, 0.f);
    #pragma unroll 2
    for (long long i = g; i < TWOP; i += stride)
        p[i] = z;

    // phase 2: idx_i/idx_j for all invalid entries (both bidirectional halves)
    int V = d_V, Vh = d_Vh;
    long long roff = P - (long long)Vh;
    for (long long tl = g; tl < P; tl += stride) {
        int t2 = (int)tl;
        unsigned w = (unsigned)t2 >> 5;
        unsigned word = __ldg(&d_mask[w]);
        unsigned lanebit = 1u << (t2 & 31);
        if (word & lanebit) continue;
        int before = __ldg(&d_bpre[w >> 10]) + __ldg(&d_wpre[w]) +
                     __popc(word & (lanebit - 1u));
        long long r1 = (long long)V + tl - before;
        long long r2 = r1 + roff;
        int bi, bj;
        if (t2 >= PCI) {
            unsigned u = (unsigned)(t2 - PCI);
            bi = (int)((u >> 10) & 1023u);
            bj = (int)(u & 1023u);
        } else {
            decodeCenter(t2, bi, bj);
        }
        float fbi = (float)bi, fbj = (float)bj;
        out[r1] = fbi;
        out[TWOP + r1] = fbj;
        out[r2] = fbj;
        out[TWOP + r2] = fbi;
    }
}

// ---- scatter the ~20K valid records (runs after writeBulk) ----
__global__ void writeValid(const float* __restrict__ box, const int* __restrict__ shifts,
                           long long P, long long TWOP, float* __restrict__ out) {
    __shared__ unsigned sb[MAXB];
    int v = blockIdx.x;
    int c = d_atomCount[v];
    if (c > MAXB) c = MAXB;
    int tid = threadIdx.x;
    for (int k = tid; k < c; k += blockDim.x) sb[k] = d_bucket[v * MAXB + k];
    __syncthreads();
    if (tid >= c) return;
    unsigned te = sb[tid];
    int rank = 0;
    for (int k = 0; k < c; k++) rank += (sb[k] < te) ? 1 : 0;
    long long r = (long long)d_atomBase[v] + rank;

    long long t = (long long)te;
    bool second = t >= P;
    int t2 = (int)(second ? t - P : t);
    int i0, j0, s;
    if (t2 >= PCI) {
        unsigned u = (unsigned)(t2 - PCI);
        s = (int)(u >> 20);
        i0 = (int)((u >> 10) & 1023u);
        j0 = (int)(u & 1023u);
    } else {
        s = -1;
        decodeCenter(t2, i0, j0);
    }
    int bi = second ? j0 : i0;
    int bj = second ? i0 : j0;
    float o0 = 0.f, o1 = 0.f, o2 = 0.f;
    if (s >= 0) {
        float sgn = second ? 1.0f : -1.0f;
        float s0 = sgn * (float)shifts[3 * s + 0];
        float s1 = sgn * (float)shifts[3 * s + 1];
        float s2 = sgn * (float)shifts[3 * s + 2];
        o0 = s0 * box[0] + s1 * box[3] + s2 * box[6];
        o1 = s0 * box[1] + s1 * box[4] + s2 * box[7];
        o2 = s0 * box[2] + s1 * box[5] + s2 * box[8];
    }
    out[r] = (float)bi;
    out[TWOP + r] = (float)bj;
    long long ob = 2 * TWOP + 3 * r;
    out[ob + 0] = o0;
    out[ob + 1] = o1;
    out[ob + 2] = o2;
    out[5 * TWOP + r] = 1.0f;
}

extern "C" void kernel_launch(void* const* d_in, const int* in_sizes, int n_in,
                              void* d_out, int out_size) {
    const float* pos  = (const float*)d_in[0];
    const float* box  = (const float*)d_in[1];
    const int* shifts = (const int*)d_in[2];

    long long TWOP = (long long)out_size / 6;    // 28,310,528
    long long P = TWOP / 2;                      // 14,155,264
    int W = (int)(P / 32);                       // 442,352
    int nScanBlocks = (W + 1023) / 1024;         // 432
    float* out = (float*)d_out;

    initK<<<1, NA>>>();
    pass1<<<OUTB + CTRB, 256>>>(pos, box, shifts, P);
    scanA<<<nScanBlocks, 1024>>>(W);
    scanB<<<1, 1024>>>(nScanBlocks);
    writeBulk<<<NB, 256>>>(P, TWOP, out);
    writeValid<<<NA, 256>>>(box, shifts, P, TWOP, out);
}

// round 8
// speedup vs baseline: 1.4120x; 1.4120x over previous
#include <cuda_runtime.h>
#include <stdint.h>

// TorchNeighborList on GB300 — R7.
// Pipeline the 453MB zero-fill across ALL kernels of the serial chain so DRAM
// never idles during pass1/scans. Roles partitioned by blockIdx; all concurrent
// writers touch disjoint regions. initK removed (globals zero-init; valid
// scatter resets d_atomCount each run for graph replays).

#define NA    1024
#define PCI   523776            // NA*(NA-1)/2
#define MAXB  256
#define CUT   5.0f
#define OUTB  1664              // outside-region pass1 blocks (13*1024/8)
#define CTRB  64                // center-region pass1 blocks
#define P1B   (OUTB + CTRB)     // 1728
#define K1ZB  3072              // zero blocks in K1
#define SCANAB 432
#define K2ZB  512
#define NIB   2048              // idx-writer blocks in K4
#define K4ZB  512
// zero-fill slice boundaries in float4 units (total TWOP float4s = 28,310,528)
#define Z1    25000000LL
#define Z2    27000000LL

__device__ unsigned d_mask[442368];     // P/32 = 442,352 words used
__device__ int      d_wpre[442368];
__device__ int      d_bsums[512];
__device__ int      d_bpre[512];
__device__ int      d_atomCount[NA];    // zero-init at load; reset each run in K4
__device__ int      d_atomBase[NA];
__device__ unsigned d_bucket[NA * MAXB];
__device__ int      d_Vh;
__device__ int      d_V;

__device__ __forceinline__ int rowstartC(int i) {
    return i * 1023 - (i * (i - 1)) / 2;
}

__device__ __forceinline__ void decodeCenter(int t2, int& i0, int& j0) {
    float q = (float)t2;
    float disc = __fsub_rn(1047552.25f, __fadd_rn(q, q));
    int i = (int)(1023.5f - __fsqrt_rn(disc));
    if (i < 0) i = 0;
    if (i > 1022) i = 1022;
    while (rowstartC(i + 1) <= t2) ++i;
    while (rowstartC(i) > t2) --i;
    i0 = i;
    j0 = t2 - rowstartC(i) + i + 1;
}

__device__ __forceinline__ void zeroSlice(float4* p, long long lo, long long hi,
                                          long long g, long long stride) {
    float4 z = make_float4(0.f, 0.f, 0.f, 0.f);
    for (long long i = lo + g; i < hi; i += stride)
        __stcs(&p[i], z);
}

// ---- K1: pass1 (blocks [0,P1B)) + zero-fill slice [0,Z1) ----
__global__ void k1(const float* __restrict__ pos, const float* __restrict__ box,
                   const int* __restrict__ shifts, long long P, long long TWOP,
                   float* __restrict__ out) {
    __shared__ float spx[NA], spy[NA], spz[NA];
    int tid = threadIdx.x;
    if (blockIdx.x >= P1B) {
        long long g = (long long)(blockIdx.x - P1B) * 256 + tid;
        zeroSlice((float4*)(out + 2 * TWOP), 0, Z1, g, (long long)K1ZB * 256);
        return;
    }
    for (int k = tid; k < NA; k += 256) {
        spx[k] = pos[3 * k + 0];
        spy[k] = pos[3 * k + 1];
        spz[k] = pos[3 * k + 2];
    }
    __syncthreads();
    if (blockIdx.x < OUTB) {
        int rowBase = blockIdx.x * 8;
        #pragma unroll 1
        for (int rr = 0; rr < 8; rr++) {
            int row = rowBase + rr;
            int s = row >> 10, i = row & 1023;
            float s0 = (float)shifts[3 * s + 0];
            float s1 = (float)shifts[3 * s + 1];
            float s2 = (float)shifts[3 * s + 2];
            float svx = s0 * box[0] + s1 * box[3] + s2 * box[6];
            float svy = s0 * box[1] + s1 * box[4] + s2 * box[7];
            float svz = s0 * box[2] + s1 * box[5] + s2 * box[8];
            float pix = spx[i], piy = spy[i], piz = spz[i];
            int t2base = PCI + (row << 10);
            #pragma unroll
            for (int c = 0; c < 4; c++) {
                int j = c * 256 + tid;
                float dx = __fadd_rn(__fsub_rn(pix, spx[j]), svx);
                float dy = __fadd_rn(__fsub_rn(piy, spy[j]), svy);
                float dz = __fadd_rn(__fsub_rn(piz, spz[j]), svz);
                float r2 = __fadd_rn(__fadd_rn(__fmul_rn(dx, dx), __fmul_rn(dy, dy)),
                                     __fmul_rn(dz, dz));
                bool valid = __fsqrt_rn(r2) < CUT;
                unsigned b = __ballot_sync(0xFFFFFFFFu, valid);
                if ((tid & 31) == 0)
                    d_mask[(t2base >> 5) + c * 8 + (tid >> 5)] = b;
                if (valid) {
                    unsigned t2 = (unsigned)(t2base + j);
                    int sl = atomicAdd(&d_atomCount[i], 1);
                    if (sl < MAXB) d_bucket[i * MAXB + sl] = t2;
                    int s2a = atomicAdd(&d_atomCount[j], 1);
                    if (s2a < MAXB) d_bucket[j * MAXB + s2a] = t2 + (unsigned)P;
                }
            }
        }
    } else {
        int cb = blockIdx.x - OUTB;
        #pragma unroll 1
        for (int c = 0; c < 32; c++) {
            int t2 = cb * 8192 + c * 256 + tid;
            bool valid = false;
            int i0 = 0, j0 = 0;
            if (t2 < PCI) {
                decodeCenter(t2, i0, j0);
                float dx = __fsub_rn(spx[i0], spx[j0]);
                float dy = __fsub_rn(spy[i0], spy[j0]);
                float dz = __fsub_rn(spz[i0], spz[j0]);
                float r2 = __fadd_rn(__fadd_rn(__fmul_rn(dx, dx), __fmul_rn(dy, dy)),
                                     __fmul_rn(dz, dz));
                valid = __fsqrt_rn(r2) < CUT;
            }
            unsigned b = __ballot_sync(0xFFFFFFFFu, valid);
            int wb = cb * 256 + c * 8 + (tid >> 5);
            if ((tid & 31) == 0 && wb < (PCI >> 5))
                d_mask[wb] = b;
            if (valid) {
                int sl = atomicAdd(&d_atomCount[i0], 1);
                if (sl < MAXB) d_bucket[i0 * MAXB + sl] = (unsigned)t2;
                int s2a = atomicAdd(&d_atomCount[j0], 1);
                if (s2a < MAXB) d_bucket[j0 * MAXB + s2a] = (unsigned)(t2 + P);
            }
        }
    }
}

// ---- K2: scanA (blocks [0,SCANAB)) + zero slice [Z1,Z2) ----
__global__ void k2(int W, long long TWOP, float* __restrict__ out) {
    if (blockIdx.x >= SCANAB) {
        long long g = (long long)(blockIdx.x - SCANAB) * 1024 + threadIdx.x;
        zeroSlice((float4*)(out + 2 * TWOP), Z1, Z2, g, (long long)K2ZB * 1024);
        return;
    }
    __shared__ int wsum[32];
    int tid = threadIdx.x, lane = tid & 31, wid = tid >> 5;
    int w = blockIdx.x * 1024 + tid;
    int v = (w < W) ? __popc(d_mask[w]) : 0;
    int x = v;
    #pragma unroll
    for (int o = 1; o < 32; o <<= 1) {
        int y = __shfl_up_sync(0xFFFFFFFFu, x, o);
        if (lane >= o) x += y;
    }
    if (lane == 31) wsum[wid] = x;
    __syncthreads();
    if (wid == 0) {
        int y = wsum[lane];
        #pragma unroll
        for (int o = 1; o < 32; o <<= 1) {
            int z = __shfl_up_sync(0xFFFFFFFFu, y, o);
            if (lane >= o) y += z;
        }
        wsum[lane] = y;
    }
    __syncthreads();
    int base = wid ? wsum[wid - 1] : 0;
    if (w < W) d_wpre[w] = base + x - v;
    if (tid == 0) d_bsums[blockIdx.x] = wsum[31];
}

// ---- K3: scanB (block sums + atom scan) ----
__global__ void k3(int nb) {
    __shared__ int wsum[32];
    int tid = threadIdx.x, lane = tid & 31, wid = tid >> 5;
    int v = (tid < nb) ? d_bsums[tid] : 0;
    int x = v;
    #pragma unroll
    for (int o = 1; o < 32; o <<= 1) {
        int y = __shfl_up_sync(0xFFFFFFFFu, x, o);
        if (lane >= o) x += y;
    }
    if (lane == 31) wsum[wid] = x;
    __syncthreads();
    if (wid == 0) {
        int y = wsum[lane];
        #pragma unroll
        for (int o = 1; o < 32; o <<= 1) {
            int z = __shfl_up_sync(0xFFFFFFFFu, y, o);
            if (lane >= o) y += z;
        }
        wsum[lane] = y;
    }
    __syncthreads();
    int base = wid ? wsum[wid - 1] : 0;
    if (tid < nb) d_bpre[tid] = base + x - v;
    if (tid == 0) { d_Vh = wsum[31]; d_V = 2 * wsum[31]; }
    __syncthreads();
    int a = d_atomCount[tid];
    int xa = a;
    #pragma unroll
    for (int o = 1; o < 32; o <<= 1) {
        int y = __shfl_up_sync(0xFFFFFFFFu, xa, o);
        if (lane >= o) xa += y;
    }
    __syncthreads();
    if (lane == 31) wsum[wid] = xa;
    __syncthreads();
    if (wid == 0) {
        int y = wsum[lane];
        #pragma unroll
        for (int o = 1; o < 32; o <<= 1) {
            int z = __shfl_up_sync(0xFFFFFFFFu, y, o);
            if (lane >= o) y += z;
        }
        wsum[lane] = y;
    }
    __syncthreads();
    int basea = wid ? wsum[wid - 1] : 0;
    d_atomBase[tid] = basea + xa - a;
}

// ---- K4: idx writer (blocks [0,NIB)) + valid scatter [NIB,NIB+NA) + zero tail ----
__global__ void k4(const float* __restrict__ box, const int* __restrict__ shifts,
                   long long P, long long TWOP, float* __restrict__ out) {
    __shared__ unsigned sb[MAXB];
    int b = blockIdx.x, tid = threadIdx.x;
    if (b < NIB) {
        int V = d_V, Vh = d_Vh;
        long long roff = P - (long long)Vh;
        long long stride = (long long)NIB * 256;
        for (long long tl = (long long)b * 256 + tid; tl < P; tl += stride) {
            int t2 = (int)tl;
            unsigned w = (unsigned)t2 >> 5;
            unsigned word = __ldg(&d_mask[w]);
            unsigned lanebit = 1u << (t2 & 31);
            if (word & lanebit) continue;
            int before = __ldg(&d_bpre[w >> 10]) + __ldg(&d_wpre[w]) +
                         __popc(word & (lanebit - 1u));
            long long r1 = (long long)V + tl - before;
            long long r2 = r1 + roff;
            int bi, bj;
            if (t2 >= PCI) {
                unsigned u = (unsigned)(t2 - PCI);
                bi = (int)((u >> 10) & 1023u);
                bj = (int)(u & 1023u);
            } else {
                decodeCenter(t2, bi, bj);
            }
            float fbi = (float)bi, fbj = (float)bj;
            __stcs(&out[r1], fbi);
            __stcs(&out[TWOP + r1], fbj);
            __stcs(&out[r2], fbj);
            __stcs(&out[TWOP + r2], fbi);
        }
    } else if (b < NIB + NA) {
        int v = b - NIB;
        int c = d_atomCount[v];
        if (c > MAXB) c = MAXB;
        for (int k = tid; k < c; k += 256) sb[k] = d_bucket[v * MAXB + k];
        __syncthreads();
        if (tid == 0) d_atomCount[v] = 0;   // reset for next graph replay
        if (tid >= c) return;
        unsigned te = sb[tid];
        int rank = 0;
        for (int k = 0; k < c; k++) rank += (sb[k] < te) ? 1 : 0;
        long long r = (long long)d_atomBase[v] + rank;

        long long t = (long long)te;
        bool second = t >= P;
        int t2 = (int)(second ? t - P : t);
        int i0, j0, s;
        if (t2 >= PCI) {
            unsigned u = (unsigned)(t2 - PCI);
            s = (int)(u >> 20);
            i0 = (int)((u >> 10) & 1023u);
            j0 = (int)(u & 1023u);
        } else {
            s = -1;
            decodeCenter(t2, i0, j0);
        }
        int bi = second ? j0 : i0;
        int bj = second ? i0 : j0;
        float o0 = 0.f, o1 = 0.f, o2 = 0.f;
        if (s >= 0) {
            float sgn = second ? 1.0f : -1.0f;
            float s0 = sgn * (float)shifts[3 * s + 0];
            float s1 = sgn * (float)shifts[3 * s + 1];
            float s2 = sgn * (float)shifts[3 * s + 2];
            o0 = s0 * box[0] + s1 * box[3] + s2 * box[6];
            o1 = s0 * box[1] + s1 * box[4] + s2 * box[7];
            o2 = s0 * box[2] + s1 * box[5] + s2 * box[8];
        }
        out[r] = (float)bi;
        out[TWOP + r] = (float)bj;
        long long ob = 2 * TWOP + 3 * r;
        out[ob + 0] = o0;
        out[ob + 1] = o1;
        out[ob + 2] = o2;
        out[5 * TWOP + r] = 1.0f;
    } else {
        long long g = (long long)(b - NIB - NA) * 256 + tid;
        zeroSlice((float4*)(out + 2 * TWOP), Z2, TWOP, g, (long long)K4ZB * 256);
    }
}

extern "C" void kernel_launch(void* const* d_in, const int* in_sizes, int n_in,
                              void* d_out, int out_size) {
    const float* pos  = (const float*)d_in[0];
    const float* box  = (const float*)d_in[1];
    const int* shifts = (const int*)d_in[2];

    long long TWOP = (long long)out_size / 6;    // 28,310,528
    long long P = TWOP / 2;                      // 14,155,264
    int W = (int)(P / 32);                       // 442,352
    float* out = (float*)d_out;

    k1<<<P1B + K1ZB, 256>>>(pos, box, shifts, P, TWOP, out);
    k2<<<SCANAB + K2ZB, 1024>>>(W, TWOP, out);
    k3<<<1, 1024>>>(SCANAB);
    k4<<<NIB + NA + K4ZB, 256>>>(box, shifts, P, TWOP, out);
}